// round 11
// baseline (speedup 1.0000x reference)
#include <cuda_runtime.h>
#include <cstdint>

// LambdaLoss: B=4096 lists, L=128 items.
// loss = mean over valid lists of
//        [ sum_{i,j: rel_i>rel_j} (rel_i-rel_j)*softplus(-(p_i-p_j)) / cnt ]
//
// softplus(-(p_w-p_l)) = ln(1 + e^{p_l}*e^{-p_w}); precompute e_i, rec_i.
// Counting-sort by rel (ascending): winner = higher sorted index -> pair
// orientation is static per pair form (no data-dependent select).
//
// R11: identical 4x4 pair engine to R10 (two warps per list, k-parity
// split), but ONE LIST PER 64-THREAD BLOCK: grid 4096. At ~40 regs this
// fits ~25 blocks/SM (50 warps) instead of 12x128-thr blocks (48 warps
// + a 1.8-block second wave); tail shrinks from ~80% of a wave to ~11%.
// Thread lj owns sorted items A..D at lj+{0,32,64,96}. Per k: 16 pairs
// covering ring distances {k, 32-k, 32+k, 64-k}. Warp0: odd k + 6
// register-only pairs; warp1: even k + k=16. 8128 pairs = C(128,2).

#define LL_B   4096
#define LL_L   128
#define LOG2E  1.4426950408889634f
#define LN2    0.6931471805599453f

__device__ float g_sum   = 0.0f;
__device__ int   g_valid = 0;
__device__ int   g_done  = 0;

__device__ __forceinline__ float fast_ex2(float x) {
    float r; asm("ex2.approx.f32 %0, %1;" : "=f"(r) : "f"(x)); return r;
}
__device__ __forceinline__ float fast_lg2(float x) {
    float r; asm("lg2.approx.f32 %0, %1;" : "=f"(r) : "f"(x)); return r;
}

__global__ __launch_bounds__(64, 24) void ll_main_kernel(
    const float* __restrict__ pred,
    const float* __restrict__ rel,
    float* __restrict__ out)
{
    // one list per block, 2 warps. S: sorted (e, rec, rel, _), +16 dup.
    __shared__ float4 S[144];
    __shared__ int    hist[8];
    __shared__ int    base[8];
    __shared__ float  wsum[2];

    const int t    = threadIdx.x;          // 0..63
    const int wl   = t >> 5;               // warp-in-list: 0 or 1
    const int lj   = t & 31;
    const int list = blockIdx.x;

    const float* P = pred + list * LL_L;
    const float* R = rel  + list * LL_L;

    // prologue: 64 threads handle 2 items each
    const float p0 = P[t],       r0 = R[t];
    const float p1 = P[t + 64],  r1 = R[t + 64];
    const int   c0 = (int)r0, c1 = (int)r1;     // rel in {0..4}
    const float q0 = p0 * LOG2E,  q1 = p1 * LOG2E;
    const float e0 = fast_ex2(q0), rc0 = fast_ex2(-q0);
    const float e1 = fast_ex2(q1), rc1 = fast_ex2(-q1);

    if (t < 8) hist[t] = 0;
    __syncthreads();
    atomicAdd(&hist[c0], 1);
    atomicAdd(&hist[c1], 1);
    __syncthreads();
    if (t == 0) {
        int a = 0;
#pragma unroll
        for (int c = 0; c < 5; c++) { base[c] = a; a += hist[c]; }
    }
    __syncthreads();
    {
        const int pos0 = atomicAdd(&base[c0], 1);
        const int pos1 = atomicAdd(&base[c1], 1);
        const float4 u0 = make_float4(e0, rc0, r0, 0.0f);
        const float4 u1 = make_float4(e1, rc1, r1, 0.0f);
        S[pos0] = u0;
        S[pos1] = u1;
        if (pos0 < 16) S[pos0 + 128] = u0;
        if (pos1 < 16) S[pos1 + 128] = u1;
    }
    __syncthreads();

    const float4 sa = S[lj];
    const float4 sb = S[lj + 32];
    const float4 sc = S[lj + 64];
    const float4 sd = S[lj + 96];
    const float eA = sa.x, cA = sa.y, rA = sa.z;
    const float eB = sb.x, cB = sb.y, rB = sb.z;
    const float eC = sc.x, cC = sc.y, rC = sc.z;
    const float eD = sd.x, cD = sd.y, rD = sd.z;

    float acc0 = 0.0f, acc1 = 0.0f, acc2 = 0.0f, acc3 = 0.0f;

    // partner (higher sorted index) wins: t = e_self*rec_p, rd = r_p - r_s >= 0
#define PW(V, ES, RS, ACC) \
    ACC = fmaf((V).z - (RS), fast_lg2(fmaf((ES), (V).y, 1.0f)), ACC);
    // self (higher sorted index) wins: t = e_p*rec_self, rd = r_s - r_p >= 0
#define SW(V, CS, RS, ACC) \
    ACC = fmaf((RS) - (V).z, fast_lg2(fmaf((V).x, (CS), 1.0f)), ACC);
    // dynamic (v4 may wrap): wrapped -> self wins, else partner wins
#define DYN(V, WR, ES, CS, RS, ACC)                                       \
    {                                                                     \
        float tt = (WR) ? fmaf((V).x, (CS), 1.0f)                         \
                        : fmaf((ES), (V).y, 1.0f);                        \
        ACC = fmaf(fabsf((V).z - (RS)), fast_lg2(tt), ACC);               \
    }

    // warp0: k = 1,3,...,13   warp1: k = 2,4,...,14 (tails below)
#pragma unroll
    for (int kk = 0; kk < 7; kk++) {
        const int k = 1 + wl + 2 * kk;
        const float4 v1 = S[lj + k];
        const float4 v2 = S[lj + 32 + k];
        const float4 v3 = S[lj + 64 + k];
        const float4 v4 = S[lj + 96 + k];
        const bool  wr = (lj + 96 + k) >= LL_L;

        // d = k
        PW(v1, eA, rA, acc0)  PW(v2, eB, rB, acc1)  PW(v3, eC, rC, acc2)
        DYN(v4, wr, eD, cD, rD, acc3)
        // d = 32+k
        PW(v2, eA, rA, acc0)  PW(v3, eB, rB, acc1)
        DYN(v4, wr, eC, cC, rC, acc2)
        SW(v1, cD, rD, acc3)
        // d = 64-k
        PW(v3, eA, rA, acc0)
        DYN(v4, wr, eB, cB, rB, acc1)
        SW(v1, cC, rC, acc2)  SW(v2, cD, rD, acc3)
        // d = 32-k
        DYN(v4, wr, eA, cA, rA, acc0)
        SW(v1, cB, rB, acc1)  SW(v2, cC, rC, acc2)  SW(v3, cD, rD, acc3)
    }

    if (wl == 0) {
        // k = 15 (last odd)
        const int k = 15;
        const float4 v1 = S[lj + k];
        const float4 v2 = S[lj + 32 + k];
        const float4 v3 = S[lj + 64 + k];
        const float4 v4 = S[lj + 96 + k];
        const bool  wr = (lj + 96 + k) >= LL_L;
        PW(v1, eA, rA, acc0)  PW(v2, eB, rB, acc1)  PW(v3, eC, rC, acc2)
        DYN(v4, wr, eD, cD, rD, acc3)
        PW(v2, eA, rA, acc0)  PW(v3, eB, rB, acc1)
        DYN(v4, wr, eC, cC, rC, acc2)
        SW(v1, cD, rD, acc3)
        PW(v3, eA, rA, acc0)
        DYN(v4, wr, eB, cB, rB, acc1)
        SW(v1, cC, rC, acc2)  SW(v2, cD, rD, acc3)
        DYN(v4, wr, eA, cA, rA, acc0)
        SW(v1, cB, rB, acc1)  SW(v2, cC, rC, acc2)  SW(v3, cD, rD, acc3)

        // register-only pairs: d=32 (A-B,B-C,C-D,D-A) and d=64 (A-C,B-D)
        acc0 = fmaf(rB - rA, fast_lg2(fmaf(eA, cB, 1.0f)), acc0);
        acc1 = fmaf(rC - rB, fast_lg2(fmaf(eB, cC, 1.0f)), acc1);
        acc2 = fmaf(rD - rC, fast_lg2(fmaf(eC, cD, 1.0f)), acc2);
        acc3 = fmaf(rD - rA, fast_lg2(fmaf(eA, cD, 1.0f)), acc3);
        acc0 = fmaf(rC - rA, fast_lg2(fmaf(eA, cC, 1.0f)), acc0);
        acc1 = fmaf(rD - rB, fast_lg2(fmaf(eB, cD, 1.0f)), acc1);
    } else {
        // k = 16: d=16 and d=48 only (other forms would duplicate)
        const float4 v1 = S[lj + 16];
        const float4 v2 = S[lj + 48];
        const float4 v3 = S[lj + 80];
        const float4 v4 = S[lj + 112];
        const bool  wr = (lj + 112) >= LL_L;
        PW(v1, eA, rA, acc0)  PW(v2, eB, rB, acc1)  PW(v3, eC, rC, acc2)
        DYN(v4, wr, eD, cD, rD, acc3)
        PW(v2, eA, rA, acc0)  PW(v3, eB, rB, acc1)
        DYN(v4, wr, eC, cC, rC, acc2)
        SW(v1, cD, rD, acc3)
    }

#undef PW
#undef SW
#undef DYN

    float acc = (acc0 + acc1) + (acc2 + acc3);

    // warp reduction, then combine the two warps
#pragma unroll
    for (int off = 16; off; off >>= 1)
        acc += __shfl_xor_sync(0xffffffffu, acc, off);
    if (lj == 0) wsum[wl] = acc;
    __syncthreads();

    if (t == 0) {
        float s = (wsum[0] + wsum[1]) * LN2;
        const int n0 = hist[0], n1 = hist[1], n2 = hist[2];
        const int n3 = hist[3], n4 = hist[4];
        const int cnt = n1 * n0
                      + n2 * (n0 + n1)
                      + n3 * (n0 + n1 + n2)
                      + n4 * (n0 + n1 + n2 + n3);
        if (cnt > 0) {
            atomicAdd(&g_sum, s / (float)cnt);
            atomicAdd(&g_valid, 1);
        }
        __threadfence();
        const int prev = atomicAdd(&g_done, 1);
        if (prev == gridDim.x - 1) {
            const float gs = g_sum;
            const int   gv = g_valid;
            out[0] = (gv > 0) ? (gs / (float)gv) : 0.0f;
            g_sum   = 0.0f;
            g_valid = 0;
            g_done  = 0;
        }
    }
}

extern "C" void kernel_launch(void* const* d_in, const int* in_sizes, int n_in,
                              void* d_out, int out_size)
{
    const float* pred = (const float*)d_in[0];
    const float* rel  = (const float*)d_in[1];
    float* out = (float*)d_out;

    ll_main_kernel<<<LL_B, 64>>>(pred, rel, out);
}